// round 7
// baseline (speedup 1.0000x reference)
#include <cuda_runtime.h>
#include <cstdint>

#define NN 50000
#define NE 800000
#define NET (NE + NN)
#define HEADS 4
#define HID 64
#define D1 256            // HEADS*HID
#define IND 128
#define EMB 128
#define NG 64

// ================= scratch =================
__device__ __align__(16) float g_h1[(size_t)NN * D1];
__device__ __align__(16) float g_act1[(size_t)NN * D1];
__device__ __align__(16) float g_h2[(size_t)NN * EMB];
__device__ __align__(16) float g_bf1[D1 / 8 * IND / 8 * 32 * 4];  // frag-ordered W1 hi/lo
__device__ __align__(16) float g_bf2[EMB / 8 * D1 / 8 * 32 * 4];  // frag-ordered W2 hi/lo
__device__ __align__(16) float g_as1[NN * HEADS];
__device__ __align__(16) float g_ad1[NN * HEADS];
__device__ __align__(16) float g_as2[NN];
__device__ __align__(16) float g_ad2[NN];
__device__ __align__(16) float g_pool[NG * EMB];
__device__ __align__(16) float g_cnt[NG];
__device__ __align__(16) int   g_src[NET];
__device__ __align__(16) int   g_dst[NET];
__device__ __align__(16) int   g_batch[NN];
__device__ __align__(16) int   g_rowptr[NN + 1];
__device__ __align__(16) int   g_wp[NN];
__device__ __align__(16) int   g_csrc[NET];

// ================= helpers =================
__device__ __forceinline__ float elu1(float x)  { return x > 0.f ? x : expm1f(x); }
__device__ __forceinline__ float lrelu(float x) { return x > 0.f ? x : 0.2f * x; }
__device__ __forceinline__ void red4(float* p, float a, float b, float c, float d) {
    asm volatile("red.global.add.v4.f32 [%0], {%1, %2, %3, %4};"
                 :: "l"(p), "f"(a), "f"(b), "f"(c), "f"(d) : "memory");
}
__device__ __forceinline__ void red1(float* p, float a) {
    asm volatile("red.global.add.f32 [%0], %1;" :: "l"(p), "f"(a) : "memory");
}
__device__ __forceinline__ float tf32_rn(float x) {
    uint32_t u; asm("cvt.rna.tf32.f32 %0, %1;" : "=r"(u) : "f"(x));
    return __uint_as_float(u);
}
// m16n8k8 tf32 mma: D += A*B  (row.col; 4 A regs, 2 B regs, 4 fp32 accum)
__device__ __forceinline__ void mma8(float* d, uint4 a, uint32_t b0, uint32_t b1) {
    asm("mma.sync.aligned.m16n8k8.row.col.f32.tf32.tf32.f32 "
        "{%0,%1,%2,%3}, {%4,%5,%6,%7}, {%8,%9}, {%0,%1,%2,%3};"
        : "+f"(d[0]), "+f"(d[1]), "+f"(d[2]), "+f"(d[3])
        : "r"(a.x), "r"(a.y), "r"(a.z), "r"(a.w), "r"(b0), "r"(b1));
}

// ================= prep / CSR =================
__global__ __launch_bounds__(256) void prep_kernel(const void* ei_raw, const void* b_raw) {
    const int*       e32 = (const int*)ei_raw;
    const long long* e64 = (const long long*)ei_raw;
    bool is64 = true;
#pragma unroll
    for (int i = 0; i < 16; i++) is64 &= (e32[2 * i + 1] == 0);

    int idx = blockIdx.x * blockDim.x + threadIdx.x;
    if (idx < NET) {
        int s, d;
        if (idx < NE) {
            if (is64) { s = (int)e64[idx]; d = (int)e64[NE + idx]; }
            else      { s = e32[idx];      d = e32[NE + idx]; }
        } else { s = d = idx - NE; }
        g_src[idx] = s;
        g_dst[idx] = d;
    }
    if (idx < NN) {
        g_batch[idx] = is64 ? (int)((const long long*)b_raw)[idx] : ((const int*)b_raw)[idx];
        g_wp[idx] = 0;
        g_as2[idx] = 0.f;   // gemm2 epilogue red-adds partial dots
        g_ad2[idx] = 0.f;
    }
    if (idx < NG * EMB) g_pool[idx] = 0.f;
    if (idx < NG)       g_cnt[idx]  = 0.f;
}

__global__ __launch_bounds__(256) void deg_kernel() {
    int idx = blockIdx.x * blockDim.x + threadIdx.x;
    if (idx < NET) atomicAdd(&g_wp[g_dst[idx]], 1);
    if (idx < NN)  atomicAdd(&g_cnt[g_batch[idx]], 1.f);
}

__global__ __launch_bounds__(1024) void scan_kernel() {
    __shared__ int part[1024];
    int t = threadIdx.x;
    const int CH = (NN + 1023) / 1024;
    int beg = t * CH, end = min(beg + CH, NN);
    int sum = 0;
    for (int i = beg; i < end; i++) sum += g_wp[i];
    part[t] = sum;
    __syncthreads();
    for (int off = 1; off < 1024; off <<= 1) {
        int v = (t >= off) ? part[t - off] : 0;
        __syncthreads();
        part[t] += v;
        __syncthreads();
    }
    int run = (t == 0) ? 0 : part[t - 1];
    for (int i = beg; i < end; i++) {
        int c = g_wp[i];
        g_rowptr[i] = run;
        g_wp[i] = run;
        run += c;
    }
    if (t == 1023) g_rowptr[NN] = run;
}

__global__ __launch_bounds__(256) void fill_kernel() {
    int e = blockIdx.x * blockDim.x + threadIdx.x;
    if (e >= NET) return;
    int pos = atomicAdd(&g_wp[g_dst[e]], 1);
    g_csrc[pos] = g_src[e];
}

// weights -> fragment-ordered tf32 hi/lo: [ntile][k8][lane][b0h,b1h,b0l,b1l]
__global__ __launch_bounds__(256) void wprep_kernel(
    const float* __restrict__ W, float* __restrict__ Bf, int K, int N)
{
    int idx = blockIdx.x * blockDim.x + threadIdx.x;
    if (idx >= K * N) return;
    int k = idx / N, n = idx % N;
    float v = W[idx];
    float hi = tf32_rn(v), lo = tf32_rn(v - hi);
    int base = (((n >> 3) * (K >> 3) + (k >> 3)) * 32 + (n & 7) * 4 + (k & 3)) * 4;
    int slot = ((k & 7) >= 4) ? 1 : 0;
    Bf[base + slot]     = hi;
    Bf[base + 2 + slot] = lo;
}

// ================= tf32 mma.sync GEMM (3-term compensated) =================
// C[M,N] = A[M,K] @ W[K,N]. Block tile 128x128, 8 warps: wm=wid&3 (32 rows),
// wn=wid>>2 (64 cols). Per warp: 2 mtiles x 8 ntiles of m16n8k8.
__global__ __launch_bounds__(256) void gemm_mma(
    const float* __restrict__ A, const float* __restrict__ Bf, float* __restrict__ C,
    int M, int N, int K,
    const float* __restrict__ avec, const float* __restrict__ dvec,
    float* __restrict__ as_out, float* __restrict__ ad_out, int multihead)
{
    __shared__ float sA[2][4096];   // [hi/lo], frag-major 128 rows x 32 k

    int tid = threadIdx.x, lane = tid & 31, wid = tid >> 5;
    int wm = wid & 3, wn = wid >> 2;
    int rowBase = blockIdx.x * 128, colBase = blockIdx.y * 128;
    int K8 = K >> 3;

    float acc[2][8][4];
#pragma unroll
    for (int mt = 0; mt < 2; mt++)
#pragma unroll
        for (int nt = 0; nt < 8; nt++)
#pragma unroll
            for (int j = 0; j < 4; j++) acc[mt][nt][j] = 0.f;

    for (int k0 = 0; k0 < K; k0 += 32) {
        // stage A chunk 128x32 -> hi/lo fragment-major
#pragma unroll
        for (int i = 0; i < 4; i++) {
            int fid = tid + 256 * i;          // 0..1023 float4s
            int r = fid >> 3, kq = fid & 7;
            int row = rowBase + r;
            float4 v = make_float4(0.f, 0.f, 0.f, 0.f);
            if (row < M) v = *(const float4*)(A + (size_t)row * K + k0 + kq * 4);
            int mt = r >> 4, rr = r & 15;
            int k8 = kq >> 1;
            int jb = (rr >= 8 ? 1 : 0) + ((kq & 1) ? 2 : 0);
            int lb = (rr & 7) * 4;
            int ob = ((mt * 4 + k8) * 32) * 4 + jb;
            float e[4] = {v.x, v.y, v.z, v.w};
#pragma unroll
            for (int q = 0; q < 4; q++) {
                float hi = tf32_rn(e[q]);
                float lo = tf32_rn(e[q] - hi);
                int off = ob + (lb + q) * 4;
                sA[0][off] = hi;
                sA[1][off] = lo;
            }
        }
        __syncthreads();

#pragma unroll
        for (int k8 = 0; k8 < 4; k8++) {
            int k8g = (k0 >> 3) + k8;
            uint4 ah[2], al[2];
#pragma unroll
            for (int mt = 0; mt < 2; mt++) {
                int mtg = wm * 2 + mt;
                int off = ((mtg * 4 + k8) * 32 + lane) * 4;
                ah[mt] = *(const uint4*)&sA[0][off];
                al[mt] = *(const uint4*)&sA[1][off];
            }
#pragma unroll
            for (int nt = 0; nt < 8; nt++) {
                // GLOBAL ntile: include colBase (R6 bug: block-local index read
                // wrong weight fragments for grid.y > 0)
                int ntG = (colBase >> 3) + wn * 8 + nt;
                uint4 b = *(const uint4*)(Bf + ((size_t)(ntG * K8 + k8g) * 32 + lane) * 4);
                // b: {b0hi, b1hi, b0lo, b1lo}
#pragma unroll
                for (int mt = 0; mt < 2; mt++) {
                    mma8(acc[mt][nt], ah[mt], b.x, b.y);   // Ahi*Bhi
                    mma8(acc[mt][nt], ah[mt], b.z, b.w);   // Ahi*Blo
                    mma8(acc[mt][nt], al[mt], b.x, b.y);   // Alo*Bhi
                }
            }
        }
        __syncthreads();
    }

    // epilogue: store C + fused attention dots
    int g = lane >> 2, q = lane & 3;
    int stripCol = colBase + wn * 64;
#pragma unroll
    for (int mt = 0; mt < 2; mt++) {
#pragma unroll
        for (int half = 0; half < 2; half++) {
            int row = rowBase + wm * 32 + mt * 16 + g + half * 8;
            float ds = 0.f, dd = 0.f;
            if (row < M) {
                float* cp = C + (size_t)row * N + stripCol;
#pragma unroll
                for (int nt = 0; nt < 8; nt++) {
                    float c0 = acc[mt][nt][half * 2], c1 = acc[mt][nt][half * 2 + 1];
                    int col = nt * 8 + q * 2;
                    *(float2*)(cp + col) = make_float2(c0, c1);
                    float a0 = avec[stripCol + col], a1 = avec[stripCol + col + 1];
                    float d0 = dvec[stripCol + col], d1 = dvec[stripCol + col + 1];
                    ds += c0 * a0 + c1 * a1;
                    dd += c0 * d0 + c1 * d1;
                }
            }
            ds += __shfl_xor_sync(0xffffffffu, ds, 1);
            ds += __shfl_xor_sync(0xffffffffu, ds, 2);
            dd += __shfl_xor_sync(0xffffffffu, dd, 1);
            dd += __shfl_xor_sync(0xffffffffu, dd, 2);
            if (q == 0 && row < M) {
                if (multihead) {
                    int head = stripCol >> 6;
                    as_out[row * 4 + head] = ds;
                    ad_out[row * 4 + head] = dd;
                } else {
                    red1(&as_out[row], ds);
                    red1(&ad_out[row], dd);
                }
            }
        }
    }
}

// ================= CSR aggregation (warp per dst node) =================
__global__ __launch_bounds__(256) void agg1_kernel(const float* __restrict__ b1) {
    int d = (blockIdx.x * blockDim.x + threadIdx.x) >> 5;
    int lane = threadIdx.x & 31;
    if (d >= NN) return;
    int h = lane >> 3;
    float ad = g_ad1[d * 4 + h];
    int beg = g_rowptr[d], end = g_rowptr[d + 1];
    float z = 0.f;
    float4 a0 = make_float4(0.f, 0.f, 0.f, 0.f);
    float4 a1 = make_float4(0.f, 0.f, 0.f, 0.f);
    for (int i = beg; i < end; i++) {
        int s = g_csrc[i];
        float w = __expf(lrelu(g_as1[s * 4 + h] + ad));
        z += w;
        const float4* hp = (const float4*)(g_h1 + (long long)s * D1);
        float4 v0 = hp[lane * 2], v1 = hp[lane * 2 + 1];
        a0.x += w * v0.x; a0.y += w * v0.y; a0.z += w * v0.z; a0.w += w * v0.w;
        a1.x += w * v1.x; a1.y += w * v1.y; a1.z += w * v1.z; a1.w += w * v1.w;
    }
    float inv = 1.f / z;
    const float4* bb = (const float4*)(b1 + lane * 8);
    float4 c0 = bb[0], c1 = bb[1];
    float4 o0, o1;
    o0.x = elu1(a0.x * inv + c0.x); o0.y = elu1(a0.y * inv + c0.y);
    o0.z = elu1(a0.z * inv + c0.z); o0.w = elu1(a0.w * inv + c0.w);
    o1.x = elu1(a1.x * inv + c1.x); o1.y = elu1(a1.y * inv + c1.y);
    o1.z = elu1(a1.z * inv + c1.z); o1.w = elu1(a1.w * inv + c1.w);
    float4* op = (float4*)(g_act1 + (long long)d * D1);
    op[lane * 2] = o0; op[lane * 2 + 1] = o1;
}

__global__ __launch_bounds__(256) void agg2_kernel(const float* __restrict__ b2) {
    int d = (blockIdx.x * blockDim.x + threadIdx.x) >> 5;
    int lane = threadIdx.x & 31;
    if (d >= NN) return;
    float ad = g_ad2[d];
    int beg = g_rowptr[d], end = g_rowptr[d + 1];
    float z = 0.f;
    float4 a = make_float4(0.f, 0.f, 0.f, 0.f);
    for (int i = beg; i < end; i++) {
        int s = g_csrc[i];
        float w = __expf(lrelu(g_as2[s] + ad));
        z += w;
        float4 v = ((const float4*)(g_h2 + (long long)s * EMB))[lane];
        a.x += w * v.x; a.y += w * v.y; a.z += w * v.z; a.w += w * v.w;
    }
    float inv = 1.f / z;
    float4 c = ((const float4*)b2)[lane];
    float o0 = elu1(a.x * inv + c.x), o1 = elu1(a.y * inv + c.y);
    float o2 = elu1(a.z * inv + c.z), o3 = elu1(a.w * inv + c.w);
    int b = g_batch[d];
    red4(&g_pool[b * EMB + lane * 4], o0, o1, o2, o3);
}

__global__ __launch_bounds__(256) void final_div_kernel(float* __restrict__ out) {
    int i = blockIdx.x * blockDim.x + threadIdx.x;
    if (i >= NG * EMB) return;
    out[i] = g_pool[i] / fmaxf(g_cnt[i >> 7], 1.f);
}

// ================= launcher =================
extern "C" void kernel_launch(void* const* d_in, const int* in_sizes, int n_in,
                              void* d_out, int out_size)
{
    const float* x      = (const float*)d_in[0];
    const void*  ei     = d_in[1];
    const void*  batch  = d_in[3];
    const float* W1     = (const float*)d_in[4];
    const float* a_src1 = (const float*)d_in[5];
    const float* a_dst1 = (const float*)d_in[6];
    const float* b1     = (const float*)d_in[7];
    const float* W2     = (const float*)d_in[8];
    const float* a_src2 = (const float*)d_in[9];
    const float* a_dst2 = (const float*)d_in[10];
    const float* b2     = (const float*)d_in[11];
    float*       out    = (float*)d_out;

    float *p_h1, *p_act1, *p_h2, *p_bf1, *p_bf2;
    float *p_as1, *p_ad1, *p_as2, *p_ad2;
    cudaGetSymbolAddress((void**)&p_h1,   g_h1);
    cudaGetSymbolAddress((void**)&p_act1, g_act1);
    cudaGetSymbolAddress((void**)&p_h2,   g_h2);
    cudaGetSymbolAddress((void**)&p_bf1,  g_bf1);
    cudaGetSymbolAddress((void**)&p_bf2,  g_bf2);
    cudaGetSymbolAddress((void**)&p_as1,  g_as1);
    cudaGetSymbolAddress((void**)&p_ad1,  g_ad1);
    cudaGetSymbolAddress((void**)&p_as2,  g_as2);
    cudaGetSymbolAddress((void**)&p_ad2,  g_ad2);

    // CSR build + weight fragment prep
    prep_kernel<<<(NET + 255) / 256, 256>>>(ei, batch);
    deg_kernel<<<(NET + 255) / 256, 256>>>();
    scan_kernel<<<1, 1024>>>();
    fill_kernel<<<(NET + 255) / 256, 256>>>();
    wprep_kernel<<<(IND * D1 + 255) / 256, 256>>>(W1, p_bf1, IND, D1);
    wprep_kernel<<<(D1 * EMB + 255) / 256, 256>>>(W2, p_bf2, D1, EMB);

    // layer 1: tensor GEMM + fused alpha dots, then CSR aggregation
    gemm_mma<<<dim3((NN + 127) / 128, D1 / 128), 256>>>(
        x, p_bf1, p_h1, NN, D1, IND, a_src1, a_dst1, p_as1, p_ad1, 1);
    agg1_kernel<<<(NN + 7) / 8, 256>>>(b1);

    // layer 2
    gemm_mma<<<dim3((NN + 127) / 128, EMB / 128), 256>>>(
        p_act1, p_bf2, p_h2, NN, EMB, D1, a_src2, a_dst2, p_as2, p_ad2, 0);
    agg2_kernel<<<(NN + 7) / 8, 256>>>(b2);

    final_div_kernel<<<(NG * EMB + 255) / 256, 256>>>(out);
}

// round 8
// speedup vs baseline: 1.0620x; 1.0620x over previous
#include <cuda_runtime.h>

#define NN 50000
#define NE 800000
#define NET (NE + NN)
#define HEADS 4
#define HID 64
#define D1 256            // HEADS*HID
#define IND 128
#define EMB 128
#define NG 64

typedef unsigned long long ull;

// ---------------- scratch ----------------
__device__ __align__(16) float g_h1[(size_t)NN * D1];
__device__ __align__(16) float g_act1[(size_t)NN * D1];   // elu(agg1 + b1)
__device__ __align__(16) float g_h2[(size_t)NN * EMB];
__device__ __align__(16) float g_as1[NN * HEADS];
__device__ __align__(16) float g_ad1[NN * HEADS];
__device__ __align__(16) float g_as2[NN];
__device__ __align__(16) float g_ad2[NN];
__device__ __align__(16) float g_pool[NG * EMB];
__device__ __align__(16) float g_cnt[NG];
__device__ __align__(16) int   g_src[NET];
__device__ __align__(16) int   g_dst[NET];
__device__ __align__(16) int   g_batch[NN];
__device__ __align__(16) int   g_rowptr[NN + 1];
__device__ __align__(16) int   g_wp[NN];
__device__ __align__(16) int   g_csrc[NET];   // src ids grouped by dst

// ---------------- helpers ----------------
__device__ __forceinline__ float elu1(float x)  { return x > 0.f ? x : expm1f(x); }
__device__ __forceinline__ float lrelu(float x) { return x > 0.f ? x : 0.2f * x; }

__device__ __forceinline__ void red4(float* p, float a, float b, float c, float d) {
    asm volatile("red.global.add.v4.f32 [%0], {%1, %2, %3, %4};"
                 :: "l"(p), "f"(a), "f"(b), "f"(c), "f"(d) : "memory");
}
__device__ __forceinline__ void ffma2(ull& d, ull a, ull b) {
    asm("fma.rn.f32x2 %0, %1, %2, %0;" : "+l"(d) : "l"(a), "l"(b));
}
__device__ __forceinline__ ull pack2(float lo, float hi) {
    ull r; asm("mov.b64 %0, {%1, %2};" : "=l"(r) : "f"(lo), "f"(hi)); return r;
}
__device__ __forceinline__ void unpack2(float& lo, float& hi, ull v) {
    asm("mov.b64 {%0, %1}, %2;" : "=f"(lo), "=f"(hi) : "l"(v));
}

// ---------------- prep: dtype-robust indices + zero small scratch ----------------
__global__ __launch_bounds__(256) void prep_kernel(const void* ei_raw, const void* b_raw) {
    const int*       e32 = (const int*)ei_raw;
    const long long* e64 = (const long long*)ei_raw;
    bool is64 = true;
#pragma unroll
    for (int i = 0; i < 16; i++) is64 &= (e32[2 * i + 1] == 0);

    int idx = blockIdx.x * blockDim.x + threadIdx.x;
    if (idx < NET) {
        int s, d;
        if (idx < NE) {
            if (is64) { s = (int)e64[idx]; d = (int)e64[NE + idx]; }
            else      { s = e32[idx];      d = e32[NE + idx]; }
        } else { s = d = idx - NE; }
        g_src[idx] = s;
        g_dst[idx] = d;
    }
    if (idx < NN) {
        g_batch[idx] = is64 ? (int)((const long long*)b_raw)[idx] : ((const int*)b_raw)[idx];
        g_wp[idx] = 0;
    }
    if (idx < NG * EMB) g_pool[idx] = 0.f;
    if (idx < NG)       g_cnt[idx]  = 0.f;
}

// degree count (into g_wp) + per-graph node counts
__global__ __launch_bounds__(256) void deg_kernel() {
    int idx = blockIdx.x * blockDim.x + threadIdx.x;
    if (idx < NET) atomicAdd(&g_wp[g_dst[idx]], 1);
    if (idx < NN)  atomicAdd(&g_cnt[g_batch[idx]], 1.f);
}

// single-block exclusive scan of degrees -> rowptr; g_wp becomes write cursor
__global__ __launch_bounds__(1024) void scan_kernel() {
    __shared__ int part[1024];
    int t = threadIdx.x;
    const int CH = (NN + 1023) / 1024;
    int beg = t * CH, end = min(beg + CH, NN);
    int sum = 0;
    for (int i = beg; i < end; i++) sum += g_wp[i];
    part[t] = sum;
    __syncthreads();
    for (int off = 1; off < 1024; off <<= 1) {
        int v = (t >= off) ? part[t - off] : 0;
        __syncthreads();
        part[t] += v;
        __syncthreads();
    }
    int run = (t == 0) ? 0 : part[t - 1];
    for (int i = beg; i < end; i++) {
        int c = g_wp[i];
        g_rowptr[i] = run;
        g_wp[i] = run;
        run += c;
    }
    if (t == 1023) g_rowptr[NN] = run;
}

__global__ __launch_bounds__(256) void fill_kernel() {
    int e = blockIdx.x * blockDim.x + threadIdx.x;
    if (e >= NET) return;
    int pos = atomicAdd(&g_wp[g_dst[e]], 1);
    g_csrc[pos] = g_src[e];
}

// ---------------- f32x2 GEMM, double-buffered: C[M,N] = A[M,K] @ B[K,N] ----------------
// BM=128, BN=128, BK=8, 256 threads, 8x8 per thread (M-paired f32x2 accum).
// Chunk c+1's global loads are prefetched into registers during chunk c's
// FFMA2 loop; single __syncthreads per chunk.
__global__ __launch_bounds__(256, 2) void gemm_kernel(
    const float* __restrict__ A, const float* __restrict__ B, float* __restrict__ C,
    int M, int N, int K)
{
    __shared__ float As[2][8][132];
    __shared__ float Bs[2][8][132];

    int tid = threadIdx.x;
    int rowBase = blockIdx.x * 128;
    int colBase = blockIdx.y * 128;
    int tx = tid & 15;             // n-tile 0..15
    int ty = tid >> 4;             // m-tile 0..15

    ull acc[4][8];
#pragma unroll
    for (int p = 0; p < 4; p++)
#pragma unroll
        for (int j = 0; j < 8; j++) acc[p][j] = 0ull;

    int arow = rowBase + (tid >> 1);
    int akoff = (tid & 1) * 4;
    int brow = tid >> 5;             // 0..7
    int bcol = colBase + (tid & 31) * 4;
    int r = tid >> 1;

    float4 av, bv;
    // prologue: chunk 0
    av = make_float4(0.f, 0.f, 0.f, 0.f);
    if (arow < M) av = *(const float4*)(A + (long long)arow * K + akoff);
    bv = *(const float4*)(B + (long long)brow * N + bcol);
    As[0][akoff + 0][r] = av.x; As[0][akoff + 1][r] = av.y;
    As[0][akoff + 2][r] = av.z; As[0][akoff + 3][r] = av.w;
    *(float4*)&Bs[0][brow][(tid & 31) * 4] = bv;
    __syncthreads();

    int nch = K >> 3;
    for (int ch = 0; ch < nch; ch++) {
        int buf = ch & 1;
        bool more = (ch + 1) < nch;
        if (more) {
            int k0 = (ch + 1) << 3;
            av = make_float4(0.f, 0.f, 0.f, 0.f);
            if (arow < M) av = *(const float4*)(A + (long long)arow * K + k0 + akoff);
            bv = *(const float4*)(B + (long long)(k0 + brow) * N + bcol);
        }
#pragma unroll
        for (int kk = 0; kk < 8; kk++) {
            ulonglong2 a01 = *(const ulonglong2*)&As[buf][kk][ty * 8];
            ulonglong2 a23 = *(const ulonglong2*)&As[buf][kk][ty * 8 + 4];
            float4 b0 = *(const float4*)&Bs[buf][kk][tx * 8];
            float4 b1 = *(const float4*)&Bs[buf][kk][tx * 8 + 4];
            ull rb[8];
            rb[0] = pack2(b0.x, b0.x); rb[1] = pack2(b0.y, b0.y);
            rb[2] = pack2(b0.z, b0.z); rb[3] = pack2(b0.w, b0.w);
            rb[4] = pack2(b1.x, b1.x); rb[5] = pack2(b1.y, b1.y);
            rb[6] = pack2(b1.z, b1.z); rb[7] = pack2(b1.w, b1.w);
            ull ra[4] = {a01.x, a01.y, a23.x, a23.y};
#pragma unroll
            for (int p = 0; p < 4; p++)
#pragma unroll
                for (int j = 0; j < 8; j++) ffma2(acc[p][j], ra[p], rb[j]);
        }
        if (more) {
            // buffer (ch+1)&1 was last READ in chunk ch-1; the sync at the end
            // of chunk ch-1 ordered those reads before these writes.
            int nb = (ch + 1) & 1;
            As[nb][akoff + 0][r] = av.x; As[nb][akoff + 1][r] = av.y;
            As[nb][akoff + 2][r] = av.z; As[nb][akoff + 3][r] = av.w;
            *(float4*)&Bs[nb][brow][(tid & 31) * 4] = bv;
        }
        __syncthreads();
    }

#pragma unroll
    for (int p = 0; p < 4; p++) {
        float lo[8], hi[8];
#pragma unroll
        for (int j = 0; j < 8; j++) unpack2(lo[j], hi[j], acc[p][j]);
        int m0 = rowBase + ty * 8 + 2 * p;
        long long cbase = (long long)m0 * N + colBase + tx * 8;
        if (m0 < M) {
            *(float4*)(C + cbase)     = make_float4(lo[0], lo[1], lo[2], lo[3]);
            *(float4*)(C + cbase + 4) = make_float4(lo[4], lo[5], lo[6], lo[7]);
        }
        if (m0 + 1 < M) {
            *(float4*)(C + cbase + N)     = make_float4(hi[0], hi[1], hi[2], hi[3]);
            *(float4*)(C + cbase + N + 4) = make_float4(hi[4], hi[5], hi[6], hi[7]);
        }
    }
}

// ---------------- attention logits ----------------
__global__ __launch_bounds__(256) void alphas1_kernel(
    const float* __restrict__ asrc, const float* __restrict__ adst)
{
    int warp = (blockIdx.x * blockDim.x + threadIdx.x) >> 5;
    int lane = threadIdx.x & 31;
    if (warp >= NN) return;
    const float4* hp = (const float4*)(g_h1 + (long long)warp * D1);
    int h = lane >> 3, sub = lane & 7;
    float4 v0 = hp[lane * 2], v1 = hp[lane * 2 + 1];
    const float4* ap = (const float4*)(asrc + h * HID + sub * 8);
    const float4* dp = (const float4*)(adst + h * HID + sub * 8);
    float4 a0 = ap[0], a1 = ap[1], d0 = dp[0], d1 = dp[1];
    float s = v0.x*a0.x + v0.y*a0.y + v0.z*a0.z + v0.w*a0.w
            + v1.x*a1.x + v1.y*a1.y + v1.z*a1.z + v1.w*a1.w;
    float d = v0.x*d0.x + v0.y*d0.y + v0.z*d0.z + v0.w*d0.w
            + v1.x*d1.x + v1.y*d1.y + v1.z*d1.z + v1.w*d1.w;
#pragma unroll
    for (int off = 4; off; off >>= 1) {
        s += __shfl_down_sync(0xffffffffu, s, off);
        d += __shfl_down_sync(0xffffffffu, d, off);
    }
    if (sub == 0) {
        g_as1[warp * 4 + h] = s;
        g_ad1[warp * 4 + h] = d;
    }
}

__global__ __launch_bounds__(256) void alphas2_kernel(
    const float* __restrict__ asrc, const float* __restrict__ adst)
{
    int warp = (blockIdx.x * blockDim.x + threadIdx.x) >> 5;
    int lane = threadIdx.x & 31;
    if (warp >= NN) return;
    float4 v = ((const float4*)(g_h2 + (long long)warp * EMB))[lane];
    float4 a = ((const float4*)asrc)[lane];
    float4 d = ((const float4*)adst)[lane];
    float s  = v.x*a.x + v.y*a.y + v.z*a.z + v.w*a.w;
    float dd = v.x*d.x + v.y*d.y + v.z*d.z + v.w*d.w;
#pragma unroll
    for (int off = 16; off; off >>= 1) {
        s  += __shfl_down_sync(0xffffffffu, s, off);
        dd += __shfl_down_sync(0xffffffffu, dd, off);
    }
    if (lane == 0) { g_as2[warp] = s; g_ad2[warp] = dd; }
}

// ---------------- CSR aggregation (warp per dst node) ----------------
__global__ __launch_bounds__(256) void agg1_kernel(const float* __restrict__ b1) {
    int d = (blockIdx.x * blockDim.x + threadIdx.x) >> 5;
    int lane = threadIdx.x & 31;
    if (d >= NN) return;
    int h = lane >> 3;
    float ad = g_ad1[d * 4 + h];
    int beg = g_rowptr[d], end = g_rowptr[d + 1];
    float z = 0.f;
    float4 a0 = make_float4(0.f, 0.f, 0.f, 0.f);
    float4 a1 = make_float4(0.f, 0.f, 0.f, 0.f);
    for (int i = beg; i < end; i++) {
        int s = g_csrc[i];
        float w = __expf(lrelu(g_as1[s * 4 + h] + ad));
        z += w;
        const float4* hp = (const float4*)(g_h1 + (long long)s * D1);
        float4 v0 = hp[lane * 2], v1 = hp[lane * 2 + 1];
        a0.x += w * v0.x; a0.y += w * v0.y; a0.z += w * v0.z; a0.w += w * v0.w;
        a1.x += w * v1.x; a1.y += w * v1.y; a1.z += w * v1.z; a1.w += w * v1.w;
    }
    float inv = 1.f / z;
    const float4* bb = (const float4*)(b1 + lane * 8);
    float4 c0 = bb[0], c1 = bb[1];
    float4 o0, o1;
    o0.x = elu1(a0.x * inv + c0.x); o0.y = elu1(a0.y * inv + c0.y);
    o0.z = elu1(a0.z * inv + c0.z); o0.w = elu1(a0.w * inv + c0.w);
    o1.x = elu1(a1.x * inv + c1.x); o1.y = elu1(a1.y * inv + c1.y);
    o1.z = elu1(a1.z * inv + c1.z); o1.w = elu1(a1.w * inv + c1.w);
    float4* op = (float4*)(g_act1 + (long long)d * D1);
    op[lane * 2] = o0; op[lane * 2 + 1] = o1;
}

__global__ __launch_bounds__(256) void agg2_kernel(const float* __restrict__ b2) {
    int d = (blockIdx.x * blockDim.x + threadIdx.x) >> 5;
    int lane = threadIdx.x & 31;
    if (d >= NN) return;
    float ad = g_ad2[d];
    int beg = g_rowptr[d], end = g_rowptr[d + 1];
    float z = 0.f;
    float4 a = make_float4(0.f, 0.f, 0.f, 0.f);
    for (int i = beg; i < end; i++) {
        int s = g_csrc[i];
        float w = __expf(lrelu(g_as2[s] + ad));
        z += w;
        float4 v = ((const float4*)(g_h2 + (long long)s * EMB))[lane];
        a.x += w * v.x; a.y += w * v.y; a.z += w * v.z; a.w += w * v.w;
    }
    float inv = 1.f / z;
    float4 c = ((const float4*)b2)[lane];
    float o0 = elu1(a.x * inv + c.x), o1 = elu1(a.y * inv + c.y);
    float o2 = elu1(a.z * inv + c.z), o3 = elu1(a.w * inv + c.w);
    int b = g_batch[d];
    red4(&g_pool[b * EMB + lane * 4], o0, o1, o2, o3);
}

__global__ __launch_bounds__(256) void final_div_kernel(float* __restrict__ out) {
    int i = blockIdx.x * blockDim.x + threadIdx.x;
    if (i >= NG * EMB) return;
    out[i] = g_pool[i] / fmaxf(g_cnt[i >> 7], 1.f);
}

// ---------------- launcher ----------------
extern "C" void kernel_launch(void* const* d_in, const int* in_sizes, int n_in,
                              void* d_out, int out_size)
{
    const float* x      = (const float*)d_in[0];
    const void*  ei     = d_in[1];
    const void*  batch  = d_in[3];
    const float* W1     = (const float*)d_in[4];
    const float* a_src1 = (const float*)d_in[5];
    const float* a_dst1 = (const float*)d_in[6];
    const float* b1     = (const float*)d_in[7];
    const float* W2     = (const float*)d_in[8];
    const float* a_src2 = (const float*)d_in[9];
    const float* a_dst2 = (const float*)d_in[10];
    const float* b2     = (const float*)d_in[11];
    float*       out    = (float*)d_out;

    float *p_h1, *p_act1, *p_h2;
    cudaGetSymbolAddress((void**)&p_h1,   g_h1);
    cudaGetSymbolAddress((void**)&p_act1, g_act1);
    cudaGetSymbolAddress((void**)&p_h2,   g_h2);

    // CSR build (shared by both layers)
    prep_kernel<<<(NET + 255) / 256, 256>>>(ei, batch);
    deg_kernel<<<(NET + 255) / 256, 256>>>();
    scan_kernel<<<1, 1024>>>();
    fill_kernel<<<(NET + 255) / 256, 256>>>();

    // layer 1
    gemm_kernel<<<dim3((NN + 127) / 128, D1 / 128), 256>>>(x, W1, p_h1, NN, D1, IND);
    alphas1_kernel<<<(NN + 7) / 8, 256>>>(a_src1, a_dst1);
    agg1_kernel<<<(NN + 7) / 8, 256>>>(b1);

    // layer 2
    gemm_kernel<<<dim3((NN + 127) / 128, EMB / 128), 256>>>(p_act1, W2, p_h2, NN, EMB, D1);
    alphas2_kernel<<<(NN + 7) / 8, 256>>>(a_src2, a_dst2);
    agg2_kernel<<<(NN + 7) / 8, 256>>>(b2);

    final_div_kernel<<<(NG * EMB + 255) / 256, 256>>>(out);
}

// round 9
// speedup vs baseline: 1.1799x; 1.1111x over previous
#include <cuda_runtime.h>

#define NN 50000
#define NE 800000
#define NET (NE + NN)
#define HEADS 4
#define HID 64
#define D1 256            // HEADS*HID
#define IND 128
#define EMB 128
#define NG 64

typedef unsigned long long ull;

// ---------------- scratch ----------------
__device__ __align__(16) float g_h1[(size_t)NN * D1];
__device__ __align__(16) float g_act1[(size_t)NN * D1];
__device__ __align__(16) float g_h2[(size_t)NN * EMB];
__device__ __align__(16) float g_as1[NN * HEADS];
__device__ __align__(16) float g_ad1[NN * HEADS];
__device__ __align__(16) float g_as2[NN];
__device__ __align__(16) float g_ad2[NN];
__device__ __align__(16) float g_pool[NG * EMB];
__device__ __align__(16) float g_cnt[NG];
__device__ __align__(16) int   g_src[NET];
__device__ __align__(16) int   g_dst[NET];
__device__ __align__(16) int   g_batch[NN];
__device__ __align__(16) int   g_rowptr[NN + 1];
__device__ __align__(16) int   g_wp[NN];
__device__ __align__(16) int   g_csrc[NET];

// ---------------- helpers ----------------
__device__ __forceinline__ float elu1(float x)  { return x > 0.f ? x : expm1f(x); }
__device__ __forceinline__ float lrelu(float x) { return x > 0.f ? x : 0.2f * x; }

__device__ __forceinline__ void red4(float* p, float a, float b, float c, float d) {
    asm volatile("red.global.add.v4.f32 [%0], {%1, %2, %3, %4};"
                 :: "l"(p), "f"(a), "f"(b), "f"(c), "f"(d) : "memory");
}
__device__ __forceinline__ void ffma2(ull& d, ull a, ull b) {
    asm("fma.rn.f32x2 %0, %1, %2, %0;" : "+l"(d) : "l"(a), "l"(b));
}
__device__ __forceinline__ ull pack2(float lo, float hi) {
    ull r; asm("mov.b64 %0, {%1, %2};" : "=l"(r) : "f"(lo), "f"(hi)); return r;
}
__device__ __forceinline__ void unpack2(float& lo, float& hi, ull v) {
    asm("mov.b64 {%0, %1}, %2;" : "=f"(lo), "=f"(hi) : "l"(v));
}

// ---------------- prep / CSR ----------------
__global__ __launch_bounds__(256) void prep_kernel(const void* ei_raw, const void* b_raw) {
    const int*       e32 = (const int*)ei_raw;
    const long long* e64 = (const long long*)ei_raw;
    bool is64 = true;
#pragma unroll
    for (int i = 0; i < 16; i++) is64 &= (e32[2 * i + 1] == 0);

    int idx = blockIdx.x * blockDim.x + threadIdx.x;
    if (idx < NET) {
        int s, d;
        if (idx < NE) {
            if (is64) { s = (int)e64[idx]; d = (int)e64[NE + idx]; }
            else      { s = e32[idx];      d = e32[NE + idx]; }
        } else { s = d = idx - NE; }
        g_src[idx] = s;
        g_dst[idx] = d;
    }
    if (idx < NN) {
        g_batch[idx] = is64 ? (int)((const long long*)b_raw)[idx] : ((const int*)b_raw)[idx];
        g_wp[idx] = 0;
    }
    if (idx < NG * EMB) g_pool[idx] = 0.f;
    if (idx < NG)       g_cnt[idx]  = 0.f;
}

__global__ __launch_bounds__(256) void deg_kernel() {
    int idx = blockIdx.x * blockDim.x + threadIdx.x;
    if (idx < NET) atomicAdd(&g_wp[g_dst[idx]], 1);
    if (idx < NN)  atomicAdd(&g_cnt[g_batch[idx]], 1.f);
}

__global__ __launch_bounds__(1024) void scan_kernel() {
    __shared__ int part[1024];
    int t = threadIdx.x;
    const int CH = (NN + 1023) / 1024;
    int beg = t * CH, end = min(beg + CH, NN);
    int sum = 0;
    for (int i = beg; i < end; i++) sum += g_wp[i];
    part[t] = sum;
    __syncthreads();
    for (int off = 1; off < 1024; off <<= 1) {
        int v = (t >= off) ? part[t - off] : 0;
        __syncthreads();
        part[t] += v;
        __syncthreads();
    }
    int run = (t == 0) ? 0 : part[t - 1];
    for (int i = beg; i < end; i++) {
        int c = g_wp[i];
        g_rowptr[i] = run;
        g_wp[i] = run;
        run += c;
    }
    if (t == 1023) g_rowptr[NN] = run;
}

__global__ __launch_bounds__(256) void fill_kernel() {
    int e = blockIdx.x * blockDim.x + threadIdx.x;
    if (e >= NET) return;
    int pos = atomicAdd(&g_wp[g_dst[e]], 1);
    g_csrc[pos] = g_src[e];
}

// ---------------- f32x2 GEMM + fused attention-dot epilogue ----------------
// C[M,N] = A[M,K] @ B[K,N]. BM=128, BN=128, BK=8, 256 threads, 8x8/thread.
// Epilogue: per-row dots with avec/dvec over this block's 128 cols.
// Thread cols (tx*8..tx*8+7) sit inside one 64-col head; shfl_xor 1/2/4
// reduces the 8 tx-lanes of a head (+xor 8 merges halves when multihead=0).
__global__ __launch_bounds__(256, 2) void gemm_kernel(
    const float* __restrict__ A, const float* __restrict__ B, float* __restrict__ C,
    int M, int N, int K,
    const float* __restrict__ avec, const float* __restrict__ dvec,
    float* __restrict__ as_out, float* __restrict__ ad_out, int multihead)
{
    __shared__ float As[8][132];
    __shared__ float Bs[8][132];

    int tid = threadIdx.x;
    int lane = tid & 31;
    int rowBase = blockIdx.x * 128;
    int colBase = blockIdx.y * 128;
    int tx = tid & 15;
    int ty = tid >> 4;

    ull acc[4][8];
#pragma unroll
    for (int p = 0; p < 4; p++)
#pragma unroll
        for (int j = 0; j < 8; j++) acc[p][j] = 0ull;

    int arow = rowBase + (tid >> 1);
    int akoff = (tid & 1) * 4;
    int brow = tid >> 5;
    int bcol = colBase + (tid & 31) * 4;
    int r = tid >> 1;

    for (int k0 = 0; k0 < K; k0 += 8) {
        float4 av = make_float4(0.f, 0.f, 0.f, 0.f);
        if (arow < M) av = *(const float4*)(A + (long long)arow * K + k0 + akoff);
        float4 bv = *(const float4*)(B + (long long)(k0 + brow) * N + bcol);
        As[akoff + 0][r] = av.x; As[akoff + 1][r] = av.y;
        As[akoff + 2][r] = av.z; As[akoff + 3][r] = av.w;
        *(float4*)&Bs[brow][(tid & 31) * 4] = bv;
        __syncthreads();
#pragma unroll
        for (int kk = 0; kk < 8; kk++) {
            ulonglong2 a01 = *(const ulonglong2*)&As[kk][ty * 8];
            ulonglong2 a23 = *(const ulonglong2*)&As[kk][ty * 8 + 4];
            float4 b0 = *(const float4*)&Bs[kk][tx * 8];
            float4 b1 = *(const float4*)&Bs[kk][tx * 8 + 4];
            ull rb[8];
            rb[0] = pack2(b0.x, b0.x); rb[1] = pack2(b0.y, b0.y);
            rb[2] = pack2(b0.z, b0.z); rb[3] = pack2(b0.w, b0.w);
            rb[4] = pack2(b1.x, b1.x); rb[5] = pack2(b1.y, b1.y);
            rb[6] = pack2(b1.z, b1.z); rb[7] = pack2(b1.w, b1.w);
            ull ra[4] = {a01.x, a01.y, a23.x, a23.y};
#pragma unroll
            for (int p = 0; p < 4; p++)
#pragma unroll
                for (int j = 0; j < 8; j++) ffma2(acc[p][j], ra[p], rb[j]);
        }
        __syncthreads();
    }

    // ---- epilogue: store C + fused attention dots ----
    float4 av0 = *(const float4*)(avec + colBase + tx * 8);
    float4 av1 = *(const float4*)(avec + colBase + tx * 8 + 4);
    float4 dv0 = *(const float4*)(dvec + colBase + tx * 8);
    float4 dv1 = *(const float4*)(dvec + colBase + tx * 8 + 4);
    float ds[8], dd[8];

#pragma unroll
    for (int p = 0; p < 4; p++) {
        float lo[8], hi[8];
#pragma unroll
        for (int j = 0; j < 8; j++) unpack2(lo[j], hi[j], acc[p][j]);
        int m0 = rowBase + ty * 8 + 2 * p;
        long long cbase = (long long)m0 * N + colBase + tx * 8;
        if (m0 < M) {
            *(float4*)(C + cbase)     = make_float4(lo[0], lo[1], lo[2], lo[3]);
            *(float4*)(C + cbase + 4) = make_float4(lo[4], lo[5], lo[6], lo[7]);
        }
        if (m0 + 1 < M) {
            *(float4*)(C + cbase + N)     = make_float4(hi[0], hi[1], hi[2], hi[3]);
            *(float4*)(C + cbase + N + 4) = make_float4(hi[4], hi[5], hi[6], hi[7]);
        }
        ds[2*p]   = lo[0]*av0.x + lo[1]*av0.y + lo[2]*av0.z + lo[3]*av0.w
                  + lo[4]*av1.x + lo[5]*av1.y + lo[6]*av1.z + lo[7]*av1.w;
        dd[2*p]   = lo[0]*dv0.x + lo[1]*dv0.y + lo[2]*dv0.z + lo[3]*dv0.w
                  + lo[4]*dv1.x + lo[5]*dv1.y + lo[6]*dv1.z + lo[7]*dv1.w;
        ds[2*p+1] = hi[0]*av0.x + hi[1]*av0.y + hi[2]*av0.z + hi[3]*av0.w
                  + hi[4]*av1.x + hi[5]*av1.y + hi[6]*av1.z + hi[7]*av1.w;
        dd[2*p+1] = hi[0]*dv0.x + hi[1]*dv0.y + hi[2]*dv0.z + hi[3]*dv0.w
                  + hi[4]*dv1.x + hi[5]*dv1.y + hi[6]*dv1.z + hi[7]*dv1.w;
    }
#pragma unroll
    for (int rr = 0; rr < 8; rr++) {
        ds[rr] += __shfl_xor_sync(0xffffffffu, ds[rr], 1);
        ds[rr] += __shfl_xor_sync(0xffffffffu, ds[rr], 2);
        ds[rr] += __shfl_xor_sync(0xffffffffu, ds[rr], 4);
        dd[rr] += __shfl_xor_sync(0xffffffffu, dd[rr], 1);
        dd[rr] += __shfl_xor_sync(0xffffffffu, dd[rr], 2);
        dd[rr] += __shfl_xor_sync(0xffffffffu, dd[rr], 4);
        if (!multihead) {
            ds[rr] += __shfl_xor_sync(0xffffffffu, ds[rr], 8);
            dd[rr] += __shfl_xor_sync(0xffffffffu, dd[rr], 8);
        }
    }
    int rowb = rowBase + ty * 8;
    if (multihead) {
        if ((lane & 7) == 0) {
            int head = (colBase >> 6) + ((lane >> 3) & 1);
#pragma unroll
            for (int rr = 0; rr < 8; rr++) {
                int row = rowb + rr;
                if (row < M) {
                    as_out[row * 4 + head] = ds[rr];
                    ad_out[row * 4 + head] = dd[rr];
                }
            }
        }
    } else {
        if ((lane & 15) == 0) {
#pragma unroll
            for (int rr = 0; rr < 8; rr++) {
                int row = rowb + rr;
                if (row < M) {
                    as_out[row] = ds[rr];
                    ad_out[row] = dd[rr];
                }
            }
        }
    }
}

// ---------------- CSR aggregation (warp per dst node) ----------------
__global__ __launch_bounds__(256) void agg1_kernel(const float* __restrict__ b1) {
    int d = (blockIdx.x * blockDim.x + threadIdx.x) >> 5;
    int lane = threadIdx.x & 31;
    if (d >= NN) return;
    int h = lane >> 3;
    float ad = g_ad1[d * 4 + h];
    int beg = g_rowptr[d], end = g_rowptr[d + 1];
    float z = 0.f;
    float4 a0 = make_float4(0.f, 0.f, 0.f, 0.f);
    float4 a1 = make_float4(0.f, 0.f, 0.f, 0.f);
    for (int i = beg; i < end; i++) {
        int s = g_csrc[i];
        float w = __expf(lrelu(g_as1[s * 4 + h] + ad));
        z += w;
        const float4* hp = (const float4*)(g_h1 + (long long)s * D1);
        float4 v0 = hp[lane * 2], v1 = hp[lane * 2 + 1];
        a0.x += w * v0.x; a0.y += w * v0.y; a0.z += w * v0.z; a0.w += w * v0.w;
        a1.x += w * v1.x; a1.y += w * v1.y; a1.z += w * v1.z; a1.w += w * v1.w;
    }
    float inv = 1.f / z;
    const float4* bb = (const float4*)(b1 + lane * 8);
    float4 c0 = bb[0], c1 = bb[1];
    float4 o0, o1;
    o0.x = elu1(a0.x * inv + c0.x); o0.y = elu1(a0.y * inv + c0.y);
    o0.z = elu1(a0.z * inv + c0.z); o0.w = elu1(a0.w * inv + c0.w);
    o1.x = elu1(a1.x * inv + c1.x); o1.y = elu1(a1.y * inv + c1.y);
    o1.z = elu1(a1.z * inv + c1.z); o1.w = elu1(a1.w * inv + c1.w);
    float4* op = (float4*)(g_act1 + (long long)d * D1);
    op[lane * 2] = o0; op[lane * 2 + 1] = o1;
}

__global__ __launch_bounds__(256) void agg2_kernel(const float* __restrict__ b2) {
    int d = (blockIdx.x * blockDim.x + threadIdx.x) >> 5;
    int lane = threadIdx.x & 31;
    if (d >= NN) return;
    float ad = g_ad2[d];
    int beg = g_rowptr[d], end = g_rowptr[d + 1];
    float z = 0.f;
    float4 a = make_float4(0.f, 0.f, 0.f, 0.f);
    for (int i = beg; i < end; i++) {
        int s = g_csrc[i];
        float w = __expf(lrelu(g_as2[s] + ad));
        z += w;
        float4 v = ((const float4*)(g_h2 + (long long)s * EMB))[lane];
        a.x += w * v.x; a.y += w * v.y; a.z += w * v.z; a.w += w * v.w;
    }
    float inv = 1.f / z;
    float4 c = ((const float4*)b2)[lane];
    float o0 = elu1(a.x * inv + c.x), o1 = elu1(a.y * inv + c.y);
    float o2 = elu1(a.z * inv + c.z), o3 = elu1(a.w * inv + c.w);
    int b = g_batch[d];
    red4(&g_pool[b * EMB + lane * 4], o0, o1, o2, o3);
}

__global__ __launch_bounds__(256) void final_div_kernel(float* __restrict__ out) {
    int i = blockIdx.x * blockDim.x + threadIdx.x;
    if (i >= NG * EMB) return;
    out[i] = g_pool[i] / fmaxf(g_cnt[i >> 7], 1.f);
}

// ---------------- launcher ----------------
extern "C" void kernel_launch(void* const* d_in, const int* in_sizes, int n_in,
                              void* d_out, int out_size)
{
    const float* x      = (const float*)d_in[0];
    const void*  ei     = d_in[1];
    const void*  batch  = d_in[3];
    const float* W1     = (const float*)d_in[4];
    const float* a_src1 = (const float*)d_in[5];
    const float* a_dst1 = (const float*)d_in[6];
    const float* b1     = (const float*)d_in[7];
    const float* W2     = (const float*)d_in[8];
    const float* a_src2 = (const float*)d_in[9];
    const float* a_dst2 = (const float*)d_in[10];
    const float* b2     = (const float*)d_in[11];
    float*       out    = (float*)d_out;

    float *p_h1, *p_act1, *p_h2, *p_as1, *p_ad1, *p_as2, *p_ad2;
    cudaGetSymbolAddress((void**)&p_h1,   g_h1);
    cudaGetSymbolAddress((void**)&p_act1, g_act1);
    cudaGetSymbolAddress((void**)&p_h2,   g_h2);
    cudaGetSymbolAddress((void**)&p_as1,  g_as1);
    cudaGetSymbolAddress((void**)&p_ad1,  g_ad1);
    cudaGetSymbolAddress((void**)&p_as2,  g_as2);
    cudaGetSymbolAddress((void**)&p_ad2,  g_ad2);

    // lazy host-side resources (no device memory)
    static cudaStream_t s_side = nullptr;
    static cudaEvent_t  ev_fork = nullptr, ev_join = nullptr;
    if (!s_side) {
        cudaStreamCreateWithFlags(&s_side, cudaStreamNonBlocking);
        cudaEventCreateWithFlags(&ev_fork, cudaEventDisableTiming);
        cudaEventCreateWithFlags(&ev_join, cudaEventDisableTiming);
    }

    // fork: CSR build runs concurrently with GEMM1
    cudaEventRecord(ev_fork, 0);
    cudaStreamWaitEvent(s_side, ev_fork, 0);
    prep_kernel<<<(NET + 255) / 256, 256, 0, s_side>>>(ei, batch);
    deg_kernel<<<(NET + 255) / 256, 256, 0, s_side>>>();
    scan_kernel<<<1, 1024, 0, s_side>>>();
    fill_kernel<<<(NET + 255) / 256, 256, 0, s_side>>>();
    cudaEventRecord(ev_join, s_side);

    // layer 1 GEMM (+fused alpha dots) on main stream, concurrent with CSR
    gemm_kernel<<<dim3((NN + 127) / 128, D1 / 128), 256>>>(
        x, W1, p_h1, NN, D1, IND, a_src1, a_dst1, p_as1, p_ad1, 1);

    // join: agg1 needs CSR + GEMM1
    cudaStreamWaitEvent(0, ev_join, 0);
    agg1_kernel<<<(NN + 7) / 8, 256>>>(b1);

    // layer 2
    gemm_kernel<<<dim3((NN + 127) / 128, EMB / 128), 256>>>(
        p_act1, W2, p_h2, NN, EMB, D1, a_src2, a_dst2, p_as2, p_ad2, 0);
    agg2_kernel<<<(NN + 7) / 8, 256>>>(b2);

    final_div_kernel<<<(NG * EMB + 255) / 256, 256>>>(out);
}